// round 16
// baseline (speedup 1.0000x reference)
#include <cuda_runtime.h>
#include <math.h>

// Problem constants
#define BN 4
#define KN 16
#define HW (512*512)
#define HW4 (HW/4)
#define LOG_2PI 1.8378770664093453f
#define LOG2E 1.4426950408889634f

// Reduction config
#define KG 8            // k-groups
#define KPT 2           // k per thread (KG*KPT == KN)
#define CHUNKS 32       // pixel chunks per (b, kgroup)
#define RTHREADS 256
#define NSTAT 10
#define ROWW (BN * KG * KPT * NSTAT)         // 640: g_part row width (chunk-major)

#define PXCHUNK (HW / CHUNKS)                // 8192 pixels per block
#define F4CHUNK (PXCHUNK / 4)                // 2048 float4 per class slice
#define AITER (F4CHUNK / RTHREADS)           // 8 iterations
#define PSLICE_BYTES (PXCHUNK * 4)           // 32768 bytes per class slice
#define PBYTES (KPT * PSLICE_BYTES)          // 65536 bytes staged per block
#define ASMEM (PBYTES + 16)                  // + mbarrier

#define CTHREADS 256    // pass C block

// Deterministic scratch (no allocations allowed).
// Chunk-major: g_part[chunk][ (b*KG+kg)*KPT*NSTAT + j*NSTAT + s ]
__device__ float g_part[CHUNKS * ROWW];

typedef unsigned long long u64;

__device__ __forceinline__ u64 pack2(float lo, float hi) {
    u64 r; asm("mov.b64 %0,{%1,%2};" : "=l"(r) : "f"(lo), "f"(hi)); return r;
}
__device__ __forceinline__ void unpack2(u64 v, float& lo, float& hi) {
    asm("mov.b64 {%0,%1},%2;" : "=f"(lo), "=f"(hi) : "l"(v));
}
__device__ __forceinline__ u64 fma2(u64 a, u64 b, u64 c) {
    u64 d; asm("fma.rn.f32x2 %0,%1,%2,%3;" : "=l"(d) : "l"(a), "l"(b), "l"(c)); return d;
}
__device__ __forceinline__ u64 mul2(u64 a, u64 b) {
    u64 d; asm("mul.rn.f32x2 %0,%1,%2;" : "=l"(d) : "l"(a), "l"(b)); return d;
}
__device__ __forceinline__ u64 add2(u64 a, u64 b) {
    u64 d; asm("add.rn.f32x2 %0,%1,%2;" : "=l"(d) : "l"(a), "l"(b)); return d;
}
__device__ __forceinline__ float ex2(float x) {
    float y; asm("ex2.approx.f32 %0,%1;" : "=f"(y) : "f"(x)); return y;
}
__device__ __forceinline__ u64 exp2_2(u64 t) {
    float lo, hi; unpack2(t, lo, hi);
    return pack2(ex2(lo), ex2(hi));
}
__device__ __forceinline__ float rcp(float x) {
    float y; asm("rcp.approx.f32 %0,%1;" : "=f"(y) : "f"(x)); return y;
}
__device__ __forceinline__ unsigned smem_u32(const void* p) {
    unsigned a;
    asm("{ .reg .u64 t; cvta.to.shared.u64 t, %1; cvt.u32.u64 %0, t; }" : "=r"(a) : "l"(p));
    return a;
}
__device__ __forceinline__ void mbar_wait(unsigned mbar, unsigned phase) {
    asm volatile(
        "{\n\t.reg .pred P1;\n\t"
        "W_%=:\n\t"
        "mbarrier.try_wait.parity.acquire.cta.shared::cta.b64 P1, [%0], %1, 0x989680;\n\t"
        "@P1 bra.uni D_%=;\n\t"
        "bra.uni W_%=;\n\t"
        "D_%=:\n\t}"
        :: "r"(mbar), "r"(phase) : "memory");
}

// ---------------------------------------------------------------------------
// Pass A: per-(b,k) partial sufficient statistics.
// P staged into smem via cp.async.bulk (TMA engine, no per-thread LDG for the
// 67MB stream); I read via LDG float4 (L2-resident). Scalar FMA accumulate.
// grid = (CHUNKS, KG, BN), block = RTHREADS, dynamic smem = ASMEM.
// ---------------------------------------------------------------------------
__global__ __launch_bounds__(RTHREADS)
void gmm_reduce_kernel(const float* __restrict__ P, const float* __restrict__ I) {
    extern __shared__ __align__(128) char smem[];
    const int b = blockIdx.z, kg = blockIdx.y, chunk = blockIdx.x;
    const int tid = threadIdx.x;

    const unsigned smem_base = smem_u32(smem);
    const unsigned mbar = smem_base + PBYTES;

    // ---- stage P slices (2 classes x 32KB) via bulk async copy ----
    if (tid == 0) {
        asm volatile("mbarrier.init.shared.b64 [%0], 1;" :: "r"(mbar) : "memory");
    }
    __syncthreads();
    if (tid == 0) {
        asm volatile("mbarrier.arrive.expect_tx.shared.b64 _, [%0], %1;"
                     :: "r"(mbar), "r"((unsigned)PBYTES) : "memory");
#pragma unroll
        for (int j = 0; j < KPT; j++) {
            const float* src = P + ((size_t)(b * KN + kg * KPT + j) * HW + (size_t)chunk * PXCHUNK);
            asm volatile(
                "cp.async.bulk.shared::cta.global.mbarrier::complete_tx::bytes [%0], [%1], %2, [%3];"
                :: "r"(smem_base + j * PSLICE_BYTES), "l"(src),
                   "r"((unsigned)PSLICE_BYTES), "r"(mbar) : "memory");
        }
    }

    const float4* __restrict__ I0 = (const float4*)(I + (size_t)(b * 3 + 0) * HW) + (size_t)chunk * F4CHUNK;
    const float4* __restrict__ I1 = (const float4*)(I + (size_t)(b * 3 + 1) * HW) + (size_t)chunk * F4CHUNK;
    const float4* __restrict__ I2 = (const float4*)(I + (size_t)(b * 3 + 2) * HW) + (size_t)chunk * F4CHUNK;
    const float4* __restrict__ Ps0 = (const float4*)(smem);
    const float4* __restrict__ Ps1 = (const float4*)(smem + PSLICE_BYTES);

    float acc[KPT][NSTAT];
#pragma unroll
    for (int j = 0; j < KPT; j++)
#pragma unroll
        for (int s = 0; s < NSTAT; s++) acc[j][s] = 0.0f;

    // wait for the staged P data
    mbar_wait(mbar, 0);

#pragma unroll 2
    for (int it = 0; it < AITER; it++) {
        const int f4 = it * RTHREADS + tid;
        const float4 a0 = I0[f4];
        const float4 a1 = I1[f4];
        const float4 a2 = I2[f4];
        const float4 w0 = Ps0[f4];
        const float4 w1 = Ps1[f4];

        const float x0[4] = {a0.x, a0.y, a0.z, a0.w};
        const float x1[4] = {a1.x, a1.y, a1.z, a1.w};
        const float x2[4] = {a2.x, a2.y, a2.z, a2.w};
        const float wl0[4] = {w0.x, w0.y, w0.z, w0.w};
        const float wl1[4] = {w1.x, w1.y, w1.z, w1.w};
#pragma unroll
        for (int l = 0; l < 4; l++) {
            const float v0 = x0[l], v1 = x1[l], v2 = x2[l];
            const float p00 = v0 * v0, p01 = v0 * v1, p02 = v0 * v2;
            const float p11 = v1 * v1, p12 = v1 * v2, p22 = v2 * v2;

            const float wa = wl0[l];
            acc[0][0] += wa;
            acc[0][1] = fmaf(wa, v0, acc[0][1]);
            acc[0][2] = fmaf(wa, v1, acc[0][2]);
            acc[0][3] = fmaf(wa, v2, acc[0][3]);
            acc[0][4] = fmaf(wa, p00, acc[0][4]);
            acc[0][5] = fmaf(wa, p01, acc[0][5]);
            acc[0][6] = fmaf(wa, p02, acc[0][6]);
            acc[0][7] = fmaf(wa, p11, acc[0][7]);
            acc[0][8] = fmaf(wa, p12, acc[0][8]);
            acc[0][9] = fmaf(wa, p22, acc[0][9]);

            const float wb = wl1[l];
            acc[1][0] += wb;
            acc[1][1] = fmaf(wb, v0, acc[1][1]);
            acc[1][2] = fmaf(wb, v1, acc[1][2]);
            acc[1][3] = fmaf(wb, v2, acc[1][3]);
            acc[1][4] = fmaf(wb, p00, acc[1][4]);
            acc[1][5] = fmaf(wb, p01, acc[1][5]);
            acc[1][6] = fmaf(wb, p02, acc[1][6]);
            acc[1][7] = fmaf(wb, p11, acc[1][7]);
            acc[1][8] = fmaf(wb, p12, acc[1][8]);
            acc[1][9] = fmaf(wb, p22, acc[1][9]);
        }
    }

    // warp reduce all KPT*NSTAT accumulators
#pragma unroll
    for (int j = 0; j < KPT; j++)
#pragma unroll
        for (int s = 0; s < NSTAT; s++)
#pragma unroll
            for (int off = 16; off > 0; off >>= 1)
                acc[j][s] += __shfl_down_sync(0xffffffffu, acc[j][s], off);

    __shared__ float sh[RTHREADS / 32][KPT * NSTAT];
    const int warp = tid >> 5, lane = tid & 31;
    if (lane == 0) {
#pragma unroll
        for (int j = 0; j < KPT; j++)
#pragma unroll
            for (int s = 0; s < NSTAT; s++)
                sh[warp][j * NSTAT + s] = acc[j][s];
    }
    __syncthreads();

    if (tid < KPT * NSTAT) {
        float v = 0.0f;
#pragma unroll
        for (int w = 0; w < RTHREADS / 32; w++) v += sh[w][tid];
        g_part[(size_t)chunk * ROWW + (b * KG + kg) * (KPT * NSTAT) + tid] = v;
    }
}

// ---------------------------------------------------------------------------
// Pass C: fused params-finalize + E-step (R10-exact, measured 22.9us).
// grid = (HW4/CTHREADS, BN), block = CTHREADS
// ---------------------------------------------------------------------------
__global__ __launch_bounds__(CTHREADS)
void gmm_estep_kernel(const float* __restrict__ I, float* __restrict__ out) {
    const int b = blockIdx.y;
    const int tid = threadIdx.x;
    const int p = blockIdx.x * CTHREADS + tid;

    __shared__ float raws[KN * NSTAT];
    __shared__ __align__(16) u64 spd[KN][NSTAT];

    if (tid < KN * NSTAT) {
        const int row = b * (KN * NSTAT) + tid;
        float a = 0.0f;
#pragma unroll
        for (int c = 0; c < CHUNKS; c++)
            a += g_part[(size_t)c * ROWW + row];
        raws[tid] = a;
    }
    __syncthreads();

    if (tid < KN) {
        const float* s = &raws[tid * NSTAT];
        const float SP = s[0];
        const float rd = 1.0f / (1e-5f + SP);
        const float mu0 = s[1] * rd, mu1 = s[2] * rd, mu2 = s[3] * rd;

        const float c00 = (s[4] - 2.0f * mu0 * s[1] + SP * mu0 * mu0) * rd + 1e-3f;
        const float c01 = (s[5] - mu0 * s[2] - mu1 * s[1] + SP * mu0 * mu1) * rd;
        const float c02 = (s[6] - mu0 * s[3] - mu2 * s[1] + SP * mu0 * mu2) * rd;
        const float c11 = (s[7] - 2.0f * mu1 * s[2] + SP * mu1 * mu1) * rd + 1e-3f;
        const float c12 = (s[8] - mu1 * s[3] - mu2 * s[2] + SP * mu1 * mu2) * rd;
        const float c22 = (s[9] - 2.0f * mu2 * s[3] + SP * mu2 * mu2) * rd + 1e-3f;

        const float m00 = c11 * c22 - c12 * c12;
        const float m01 = c02 * c12 - c01 * c22;
        const float m02 = c01 * c12 - c02 * c11;
        const float det = c00 * m00 + c01 * m01 + c02 * m02;
        const float inv = 1.0f / det;

        const float i00 = m00 * inv;
        const float i01 = m01 * inv;
        const float i02 = m02 * inv;
        const float i11 = (c00 * c22 - c02 * c02) * inv;
        const float i12 = (c01 * c02 - c00 * c12) * inv;
        const float i22 = (c00 * c11 - c01 * c01) * inv;

        const float alpha = SP * (1.0f / (float)HW);
        const float logcoef = logf(alpha) - 0.5f * (3.0f * LOG_2PI + logf(det));

        const float g0 = i00 * mu0 + i01 * mu1 + i02 * mu2;
        const float g1 = i01 * mu0 + i11 * mu1 + i12 * mu2;
        const float g2 = i02 * mu0 + i12 * mu1 + i22 * mu2;
        const float Pmu = 0.5f * (i00 * mu0 * mu0 + i11 * mu1 * mu1 + i22 * mu2 * mu2)
                        + i01 * mu0 * mu1 + i02 * mu0 * mu2 + i12 * mu1 * mu2;

        u64* o = spd[tid];
        const float pc0 = (logcoef - Pmu) * LOG2E;
        const float pg0 = g0 * LOG2E, pg1 = g1 * LOG2E, pg2 = g2 * LOG2E;
        const float h00 = -0.5f * i00 * LOG2E, h11 = -0.5f * i11 * LOG2E, h22 = -0.5f * i22 * LOG2E;
        const float h01 = -i01 * LOG2E, h02 = -i02 * LOG2E, h12 = -i12 * LOG2E;
        o[0] = pack2(pc0, pc0);
        o[1] = pack2(pg0, pg0);
        o[2] = pack2(pg1, pg1);
        o[3] = pack2(pg2, pg2);
        o[4] = pack2(h00, h00);
        o[5] = pack2(h11, h11);
        o[6] = pack2(h22, h22);
        o[7] = pack2(h01, h01);
        o[8] = pack2(h02, h02);
        o[9] = pack2(h12, h12);
    }
    __syncthreads();

    const float4 a0 = ((const float4*)(I + (size_t)(b * 3 + 0) * HW))[p];
    const float4 a1 = ((const float4*)(I + (size_t)(b * 3 + 1) * HW))[p];
    const float4 a2 = ((const float4*)(I + (size_t)(b * 3 + 2) * HW))[p];

    u64 X0[2], X1[2], X2[2], XX00[2], XX01[2], XX02[2], XX11[2], XX12[2], XX22[2];
#pragma unroll
    for (int pi = 0; pi < 2; pi++) {
        X0[pi] = pi ? pack2(a0.z, a0.w) : pack2(a0.x, a0.y);
        X1[pi] = pi ? pack2(a1.z, a1.w) : pack2(a1.x, a1.y);
        X2[pi] = pi ? pack2(a2.z, a2.w) : pack2(a2.x, a2.y);
        XX00[pi] = mul2(X0[pi], X0[pi]);
        XX01[pi] = mul2(X0[pi], X1[pi]);
        XX02[pi] = mul2(X0[pi], X2[pi]);
        XX11[pi] = mul2(X1[pi], X1[pi]);
        XX12[pi] = mul2(X1[pi], X2[pi]);
        XX22[pi] = mul2(X2[pi], X2[pi]);
    }

    u64 q0[KN], q1[KN];
    u64 sum0 = 0ull, sum1 = 0ull;
#pragma unroll
    for (int k = 0; k < KN; k++) {
        const ulonglong2* pr = (const ulonglong2*)spd[k];
        const ulonglong2 pA = pr[0];
        const ulonglong2 pB = pr[1];
        const ulonglong2 pC = pr[2];
        const ulonglong2 pD = pr[3];
        const ulonglong2 pE = pr[4];

        {
            u64 ta = fma2(pA.y, X0[0], pA.x);
            ta = fma2(pB.x, X1[0], ta);
            ta = fma2(pB.y, X2[0], ta);
            ta = fma2(pC.x, XX00[0], ta);
            u64 tb = mul2(pC.y, XX11[0]);
            tb = fma2(pD.x, XX22[0], tb);
            tb = fma2(pD.y, XX01[0], tb);
            tb = fma2(pE.x, XX02[0], tb);
            tb = fma2(pE.y, XX12[0], tb);
            const u64 e = exp2_2(add2(ta, tb));
            q0[k] = e;
            sum0 = add2(sum0, e);
        }
        {
            u64 ta = fma2(pA.y, X0[1], pA.x);
            ta = fma2(pB.x, X1[1], ta);
            ta = fma2(pB.y, X2[1], ta);
            ta = fma2(pC.x, XX00[1], ta);
            u64 tb = mul2(pC.y, XX11[1]);
            tb = fma2(pD.x, XX22[1], tb);
            tb = fma2(pD.y, XX01[1], tb);
            tb = fma2(pE.x, XX02[1], tb);
            tb = fma2(pE.y, XX12[1], tb);
            const u64 e = exp2_2(add2(ta, tb));
            q1[k] = e;
            sum1 = add2(sum1, e);
        }
    }

    float s0, s1, s2, s3;
    unpack2(sum0, s0, s1);
    unpack2(sum1, s2, s3);
    const u64 R0 = pack2(rcp(1e-5f + s0), rcp(1e-5f + s1));
    const u64 R1 = pack2(rcp(1e-5f + s2), rcp(1e-5f + s3));

    float4* __restrict__ o4 = (float4*)(out + (size_t)b * KN * HW);
#pragma unroll
    for (int k = 0; k < KN; k++) {
        const u64 v01 = mul2(q0[k], R0);
        const u64 v23 = mul2(q1[k], R1);
        float4 v;
        unpack2(v01, v.x, v.y);
        unpack2(v23, v.z, v.w);
        __stcs(&o4[(size_t)k * HW4 + p], v);
    }
}

// ---------------------------------------------------------------------------
// Host: enable 64KB+ dynamic smem for pass A once at load time.
// ---------------------------------------------------------------------------
namespace {
struct FuncInit {
    FuncInit() {
        cudaFuncSetAttribute(gmm_reduce_kernel,
                             cudaFuncAttributeMaxDynamicSharedMemorySize, ASMEM);
    }
};
static FuncInit g_func_init;
}

extern "C" void kernel_launch(void* const* d_in, const int* in_sizes, int n_in,
                              void* d_out, int out_size) {
    const float* Pij = (const float*)d_in[0];
    const float* I   = (const float*)d_in[1];
    float* out = (float*)d_out;

    dim3 gA(CHUNKS, KG, BN);
    gmm_reduce_kernel<<<gA, RTHREADS, ASMEM>>>(Pij, I);
    dim3 gC(HW4 / CTHREADS, BN);
    gmm_estep_kernel<<<gC, CTHREADS>>>(I, out);
}

// round 17
// speedup vs baseline: 1.1342x; 1.1342x over previous
#include <cuda_runtime.h>
#include <math.h>

// Problem constants
#define BN 4
#define KN 16
#define HW (512*512)
#define HW4 (HW/4)
#define LOG_2PI 1.8378770664093453f
#define LOG2E 1.4426950408889634f

// Reduction config
#define KG 8            // k-groups
#define KPT 2           // k per thread (KG*KPT == KN)
#define CHUNKS 32       // pixel chunks per (b, kgroup)
#define RTHREADS 256
#define RITERS (HW4 / (CHUNKS * RTHREADS))   // = 8, exact
#define NSTAT 10
#define BROWS (KN * NSTAT)                   // 160
#define ROWW (BN * BROWS)                    // 640: g_part row width (chunk-major)

#define CTHREADS 256    // estep block: 8 warps = 4 class-groups x 2 quad-groups
#define QPB 64          // pixel-quads per block

// Deterministic scratch (no allocations allowed).
// Chunk-major: g_part[chunk][ b*160 + (kg*KPT+j)*NSTAT + s ]
__device__ float g_part[CHUNKS * ROWW];

typedef unsigned long long u64;
__device__ u64 g_params[BN * BROWS];   // packed lane-duplicated affine params

__device__ __forceinline__ u64 pack2(float lo, float hi) {
    u64 r; asm("mov.b64 %0,{%1,%2};" : "=l"(r) : "f"(lo), "f"(hi)); return r;
}
__device__ __forceinline__ void unpack2(u64 v, float& lo, float& hi) {
    asm("mov.b64 {%0,%1},%2;" : "=f"(lo), "=f"(hi) : "l"(v));
}
__device__ __forceinline__ u64 fma2(u64 a, u64 b, u64 c) {
    u64 d; asm("fma.rn.f32x2 %0,%1,%2,%3;" : "=l"(d) : "l"(a), "l"(b), "l"(c)); return d;
}
__device__ __forceinline__ u64 mul2(u64 a, u64 b) {
    u64 d; asm("mul.rn.f32x2 %0,%1,%2;" : "=l"(d) : "l"(a), "l"(b)); return d;
}
__device__ __forceinline__ u64 add2(u64 a, u64 b) {
    u64 d; asm("add.rn.f32x2 %0,%1,%2;" : "=l"(d) : "l"(a), "l"(b)); return d;
}
__device__ __forceinline__ float ex2(float x) {
    float y; asm("ex2.approx.f32 %0,%1;" : "=f"(y) : "f"(x)); return y;
}
__device__ __forceinline__ u64 exp2_2(u64 t) {
    float lo, hi; unpack2(t, lo, hi);
    return pack2(ex2(lo), ex2(hi));
}
__device__ __forceinline__ float rcp(float x) {
    float y; asm("rcp.approx.f32 %0,%1;" : "=f"(y) : "f"(x)); return y;
}

// ---------------------------------------------------------------------------
// Pass A: per-(b,k) partial sufficient statistics, float4 loads, scalar FMA.
// grid = (CHUNKS, KG, BN), block = RTHREADS. (Champion config, 21.4us.)
// ---------------------------------------------------------------------------
__global__ __launch_bounds__(RTHREADS)
void gmm_reduce_kernel(const float* __restrict__ P, const float* __restrict__ I) {
    const int b = blockIdx.z, kg = blockIdx.y, chunk = blockIdx.x;
    const int tid = threadIdx.x;

    const float4* __restrict__ I0 = (const float4*)(I + (size_t)(b * 3 + 0) * HW);
    const float4* __restrict__ I1 = (const float4*)(I + (size_t)(b * 3 + 1) * HW);
    const float4* __restrict__ I2 = (const float4*)(I + (size_t)(b * 3 + 2) * HW);
    const float4* __restrict__ Pb = (const float4*)(P + ((size_t)b * KN + (size_t)kg * KPT) * HW);

    float acc[KPT][NSTAT];
#pragma unroll
    for (int j = 0; j < KPT; j++)
#pragma unroll
        for (int s = 0; s < NSTAT; s++) acc[j][s] = 0.0f;

    const int stride = CHUNKS * RTHREADS;
    int p = chunk * RTHREADS + tid;
#pragma unroll 2
    for (int it = 0; it < RITERS; it++, p += stride) {
        const float4 a0 = I0[p];
        const float4 a1 = I1[p];
        const float4 a2 = I2[p];
        float4 w[KPT];
#pragma unroll
        for (int j = 0; j < KPT; j++)
            w[j] = __ldcs(&Pb[(size_t)j * HW4 + p]);

        const float x0[4] = {a0.x, a0.y, a0.z, a0.w};
        const float x1[4] = {a1.x, a1.y, a1.z, a1.w};
        const float x2[4] = {a2.x, a2.y, a2.z, a2.w};
#pragma unroll
        for (int l = 0; l < 4; l++) {
            const float v0 = x0[l], v1 = x1[l], v2 = x2[l];
            const float p00 = v0 * v0, p01 = v0 * v1, p02 = v0 * v2;
            const float p11 = v1 * v1, p12 = v1 * v2, p22 = v2 * v2;
#pragma unroll
            for (int j = 0; j < KPT; j++) {
                const float wl = (l == 0) ? w[j].x : (l == 1) ? w[j].y : (l == 2) ? w[j].z : w[j].w;
                acc[j][0] += wl;
                acc[j][1] = fmaf(wl, v0, acc[j][1]);
                acc[j][2] = fmaf(wl, v1, acc[j][2]);
                acc[j][3] = fmaf(wl, v2, acc[j][3]);
                acc[j][4] = fmaf(wl, p00, acc[j][4]);
                acc[j][5] = fmaf(wl, p01, acc[j][5]);
                acc[j][6] = fmaf(wl, p02, acc[j][6]);
                acc[j][7] = fmaf(wl, p11, acc[j][7]);
                acc[j][8] = fmaf(wl, p12, acc[j][8]);
                acc[j][9] = fmaf(wl, p22, acc[j][9]);
            }
        }
    }

#pragma unroll
    for (int j = 0; j < KPT; j++)
#pragma unroll
        for (int s = 0; s < NSTAT; s++)
#pragma unroll
            for (int off = 16; off > 0; off >>= 1)
                acc[j][s] += __shfl_down_sync(0xffffffffu, acc[j][s], off);

    __shared__ float sh[RTHREADS / 32][KPT * NSTAT];
    const int warp = tid >> 5, lane = tid & 31;
    if (lane == 0) {
#pragma unroll
        for (int j = 0; j < KPT; j++)
#pragma unroll
            for (int s = 0; s < NSTAT; s++)
                sh[warp][j * NSTAT + s] = acc[j][s];
    }
    __syncthreads();

    if (tid < KPT * NSTAT) {
        float v = 0.0f;
#pragma unroll
        for (int w = 0; w < RTHREADS / 32; w++) v += sh[w][tid];
        g_part[(size_t)chunk * ROWW + (b * KG + kg) * (KPT * NSTAT) + tid] = v;
    }
}

// ---------------------------------------------------------------------------
// Pass B: params finalize. grid = BN blocks x 160 threads; coalesced
// chunk-major reduction (consecutive threads -> consecutive addresses).
// ---------------------------------------------------------------------------
__global__ void gmm_params_kernel() {
    const int b = blockIdx.x;
    const int t = threadIdx.x;
    __shared__ float raws[BROWS];

    if (t < BROWS) {
        const int row = b * BROWS + t;
        float a = 0.0f;
#pragma unroll
        for (int c = 0; c < CHUNKS; c++)
            a += g_part[(size_t)c * ROWW + row];
        raws[t] = a;
    }
    __syncthreads();

    if (t < KN) {
        const float* s = &raws[t * NSTAT];
        const float SP = s[0];
        const float rd = 1.0f / (1e-5f + SP);
        const float mu0 = s[1] * rd, mu1 = s[2] * rd, mu2 = s[3] * rd;

        const float c00 = (s[4] - 2.0f * mu0 * s[1] + SP * mu0 * mu0) * rd + 1e-3f;
        const float c01 = (s[5] - mu0 * s[2] - mu1 * s[1] + SP * mu0 * mu1) * rd;
        const float c02 = (s[6] - mu0 * s[3] - mu2 * s[1] + SP * mu0 * mu2) * rd;
        const float c11 = (s[7] - 2.0f * mu1 * s[2] + SP * mu1 * mu1) * rd + 1e-3f;
        const float c12 = (s[8] - mu1 * s[3] - mu2 * s[2] + SP * mu1 * mu2) * rd;
        const float c22 = (s[9] - 2.0f * mu2 * s[3] + SP * mu2 * mu2) * rd + 1e-3f;

        const float m00 = c11 * c22 - c12 * c12;
        const float m01 = c02 * c12 - c01 * c22;
        const float m02 = c01 * c12 - c02 * c11;
        const float det = c00 * m00 + c01 * m01 + c02 * m02;
        const float inv = 1.0f / det;

        const float i00 = m00 * inv;
        const float i01 = m01 * inv;
        const float i02 = m02 * inv;
        const float i11 = (c00 * c22 - c02 * c02) * inv;
        const float i12 = (c01 * c02 - c00 * c12) * inv;
        const float i22 = (c00 * c11 - c01 * c01) * inv;

        const float alpha = SP * (1.0f / (float)HW);
        const float logcoef = logf(alpha) - 0.5f * (3.0f * LOG_2PI + logf(det));

        const float g0 = i00 * mu0 + i01 * mu1 + i02 * mu2;
        const float g1 = i01 * mu0 + i11 * mu1 + i12 * mu2;
        const float g2 = i02 * mu0 + i12 * mu1 + i22 * mu2;
        const float Pmu = 0.5f * (i00 * mu0 * mu0 + i11 * mu1 * mu1 + i22 * mu2 * mu2)
                        + i01 * mu0 * mu1 + i02 * mu0 * mu2 + i12 * mu1 * mu2;

        u64* o = &g_params[(size_t)(b * KN + t) * NSTAT];
        const float pc0 = (logcoef - Pmu) * LOG2E;
        const float pg0 = g0 * LOG2E, pg1 = g1 * LOG2E, pg2 = g2 * LOG2E;
        const float h00 = -0.5f * i00 * LOG2E, h11 = -0.5f * i11 * LOG2E, h22 = -0.5f * i22 * LOG2E;
        const float h01 = -i01 * LOG2E, h02 = -i02 * LOG2E, h12 = -i12 * LOG2E;
        o[0] = pack2(pc0, pc0);
        o[1] = pack2(pg0, pg0);
        o[2] = pack2(pg1, pg1);
        o[3] = pack2(pg2, pg2);
        o[4] = pack2(h00, h00);
        o[5] = pack2(h11, h11);
        o[6] = pack2(h22, h22);
        o[7] = pack2(h01, h01);
        o[8] = pack2(h02, h02);
        o[9] = pack2(h12, h12);
    }
}

// ---------------------------------------------------------------------------
// Pass C: E-step, classes split across warps (low regs, high occupancy).
// Block = 8 warps: warp w -> class group (w&3) = classes [(w&3)*4, +4),
//                  quad group (w>>2)  -> quad = (w>>2)*32 + lane.
// Cross-warp denominator via smem exchange (deterministic fixed-order sum).
// grid = (HW4/QPB, BN), block = CTHREADS.
// ---------------------------------------------------------------------------
__global__ __launch_bounds__(CTHREADS)
void gmm_estep_kernel(const float* __restrict__ I, float* __restrict__ out) {
    const int b = blockIdx.y;
    const int tid = threadIdx.x;
    const int lane = tid & 31;
    const int w = tid >> 5;
    const int cg = w & 3;          // class group: classes [cg*4, cg*4+4)
    const int qg = w >> 2;         // quad group: 0 or 1
    const int quad = qg * 32 + lane;

    __shared__ __align__(16) u64 spd[KN * NSTAT];
    __shared__ __align__(16) ulonglong2 exch[4][QPB];

    // coalesced param load: 160 u64 in one round
    if (tid < BROWS)
        spd[tid] = g_params[(size_t)b * BROWS + tid];
    __syncthreads();

    const int p = blockIdx.x * QPB + quad;

    const float4 a0 = ((const float4*)(I + (size_t)(b * 3 + 0) * HW))[p];
    const float4 a1 = ((const float4*)(I + (size_t)(b * 3 + 1) * HW))[p];
    const float4 a2 = ((const float4*)(I + (size_t)(b * 3 + 2) * HW))[p];

    u64 X0[2], X1[2], X2[2], XX00[2], XX01[2], XX02[2], XX11[2], XX12[2], XX22[2];
#pragma unroll
    for (int pi = 0; pi < 2; pi++) {
        X0[pi] = pi ? pack2(a0.z, a0.w) : pack2(a0.x, a0.y);
        X1[pi] = pi ? pack2(a1.z, a1.w) : pack2(a1.x, a1.y);
        X2[pi] = pi ? pack2(a2.z, a2.w) : pack2(a2.x, a2.y);
        XX00[pi] = mul2(X0[pi], X0[pi]);
        XX01[pi] = mul2(X0[pi], X1[pi]);
        XX02[pi] = mul2(X0[pi], X2[pi]);
        XX11[pi] = mul2(X1[pi], X1[pi]);
        XX12[pi] = mul2(X1[pi], X2[pi]);
        XX22[pi] = mul2(X2[pi], X2[pi]);
    }

    u64 q0[4], q1[4];
    u64 psum0 = 0ull, psum1 = 0ull;
#pragma unroll
    for (int kc = 0; kc < 4; kc++) {
        const int k = cg * 4 + kc;
        const ulonglong2* pr = (const ulonglong2*)&spd[k * NSTAT];
        const ulonglong2 pA = pr[0];  // C0,  G0
        const ulonglong2 pB = pr[1];  // G1,  G2
        const ulonglong2 pC = pr[2];  // H00, H11
        const ulonglong2 pD = pr[3];  // H22, H01
        const ulonglong2 pE = pr[4];  // H02, H12

        {
            u64 ta = fma2(pA.y, X0[0], pA.x);
            ta = fma2(pB.x, X1[0], ta);
            ta = fma2(pB.y, X2[0], ta);
            ta = fma2(pC.x, XX00[0], ta);
            u64 tb = mul2(pC.y, XX11[0]);
            tb = fma2(pD.x, XX22[0], tb);
            tb = fma2(pD.y, XX01[0], tb);
            tb = fma2(pE.x, XX02[0], tb);
            tb = fma2(pE.y, XX12[0], tb);
            const u64 e = exp2_2(add2(ta, tb));
            q0[kc] = e;
            psum0 = add2(psum0, e);
        }
        {
            u64 ta = fma2(pA.y, X0[1], pA.x);
            ta = fma2(pB.x, X1[1], ta);
            ta = fma2(pB.y, X2[1], ta);
            ta = fma2(pC.x, XX00[1], ta);
            u64 tb = mul2(pC.y, XX11[1]);
            tb = fma2(pD.x, XX22[1], tb);
            tb = fma2(pD.y, XX01[1], tb);
            tb = fma2(pE.x, XX02[1], tb);
            tb = fma2(pE.y, XX12[1], tb);
            const u64 e = exp2_2(add2(ta, tb));
            q1[kc] = e;
            psum1 = add2(psum1, e);
        }
    }

    // cross-warp denominator exchange (deterministic fixed-order sum)
    exch[cg][quad] = make_ulonglong2(psum0, psum1);
    __syncthreads();
    const ulonglong2 e0 = exch[0][quad];
    const ulonglong2 e1 = exch[1][quad];
    const ulonglong2 e2 = exch[2][quad];
    const ulonglong2 e3 = exch[3][quad];
    const u64 sum0 = add2(add2(e0.x, e1.x), add2(e2.x, e3.x));
    const u64 sum1 = add2(add2(e0.y, e1.y), add2(e2.y, e3.y));

    float s0, s1, s2, s3;
    unpack2(sum0, s0, s1);
    unpack2(sum1, s2, s3);
    const u64 R0 = pack2(rcp(1e-5f + s0), rcp(1e-5f + s1));
    const u64 R1 = pack2(rcp(1e-5f + s2), rcp(1e-5f + s3));

    float4* __restrict__ o4 = (float4*)(out + (size_t)b * KN * HW);
#pragma unroll
    for (int kc = 0; kc < 4; kc++) {
        const u64 v01 = mul2(q0[kc], R0);
        const u64 v23 = mul2(q1[kc], R1);
        float4 v;
        unpack2(v01, v.x, v.y);
        unpack2(v23, v.z, v.w);
        __stcs(&o4[(size_t)(cg * 4 + kc) * HW4 + p], v);
    }
}

extern "C" void kernel_launch(void* const* d_in, const int* in_sizes, int n_in,
                              void* d_out, int out_size) {
    const float* Pij = (const float*)d_in[0];
    const float* I   = (const float*)d_in[1];
    float* out = (float*)d_out;

    dim3 gA(CHUNKS, KG, BN);
    gmm_reduce_kernel<<<gA, RTHREADS>>>(Pij, I);
    gmm_params_kernel<<<BN, 160>>>();
    dim3 gC(HW4 / QPB, BN);
    gmm_estep_kernel<<<gC, CTHREADS>>>(I, out);
}